// round 6
// baseline (speedup 1.0000x reference)
#include <cuda_runtime.h>
#include <cstddef>

// Problem constants (DNCMemory: B=64, N=1024, W=64, R=4, NW=1)
#define EPSF 1e-5f
constexpr int Bn = 64;
constexpr int Nn = 1024;
constexpr int Wn = 64;
constexpr int Rn = 4;

// ---------------------------------------------------------------------------
// reductions
// ---------------------------------------------------------------------------
__device__ __forceinline__ float warp_rsum(float v) {
#pragma unroll
    for (int o = 16; o > 0; o >>= 1) v += __shfl_xor_sync(0xffffffffu, v, o);
    return v;
}
__device__ __forceinline__ float warp_rmax(float v) {
#pragma unroll
    for (int o = 16; o > 0; o >>= 1) v = fmaxf(v, __shfl_xor_sync(0xffffffffu, v, o));
    return v;
}
// 1024-thread block reduce (32 warps), 2 barriers each
__device__ __forceinline__ float block_rsum(float v, float* s_warp, int tid) {
    v = warp_rsum(v);
    if ((tid & 31) == 0) s_warp[tid >> 5] = v;
    __syncthreads();
    if (tid < 32) {
        float x = s_warp[tid];
        x = warp_rsum(x);
        if (tid == 0) s_warp[0] = x;
    }
    __syncthreads();
    float r = s_warp[0];
    __syncthreads();
    return r;
}
__device__ __forceinline__ float block_rmax(float v, float* s_warp, int tid) {
    v = warp_rmax(v);
    if ((tid & 31) == 0) s_warp[tid >> 5] = v;
    __syncthreads();
    if (tid < 32) {
        float x = s_warp[tid];
        x = warp_rmax(x);
        if (tid == 0) s_warp[0] = x;
    }
    __syncthreads();
    float r = s_warp[0];
    __syncthreads();
    return r;
}

__device__ __forceinline__ float softplusf(float x) {
    return fmaxf(x, 0.f) + log1pf(expf(-fabsf(x)));
}

// In-warp bitonic compare-exchange for stride j (j <= 16).
// desc = descending region (tid & k) == 0. Strict comparisons: ties don't swap.
__device__ __forceinline__ void bitonic_shfl(float& v, int& ix, int j, bool desc, int tid) {
    float ov = __shfl_xor_sync(0xffffffffu, v, j);
    int   oi = __shfl_xor_sync(0xffffffffu, ix, j);
    bool am_lower = ((tid & j) == 0);
    float lowv = am_lower ? v : ov;
    float upv  = am_lower ? ov : v;
    bool sw = desc ? (lowv < upv) : (lowv > upv);
    if (sw) { v = ov; ix = oi; }
}

// ---------------------------------------------------------------------------
// Per-batch kernel: usage, cosine addressing (4 read + 1 write head with
// softmax), allocation (hybrid bitonic sort + shuffle multiplicative scan),
// write weights, precedence. One block of 1024 threads per batch.
// ---------------------------------------------------------------------------
__global__ __launch_bounds__(1024, 1) void dnc_batch_kernel(
    const float* __restrict__ memory,      // [B,N,W]
    const float* __restrict__ read_keys,   // [B,R,W]
    const float* __restrict__ read_str,    // [B,R]
    const float* __restrict__ write_keys,  // [B,1,W]
    const float* __restrict__ write_str,   // [B,1]
    const float* __restrict__ free_gate,   // [B,R]
    const float* __restrict__ alloc_gate,  // [B,1]
    const float* __restrict__ write_gate,  // [B,1]
    const float* __restrict__ prev_rw,     // [B,R,N]
    const float* __restrict__ prev_ww,     // [B,1,N]
    const float* __restrict__ prev_usage,  // [B,N]
    const float* __restrict__ prev_prec,   // [B,1,N]
    float* __restrict__ out_rw,            // [B,R,N]
    float* __restrict__ out_ww,            // [B,N]
    float* __restrict__ out_usage,         // [B,N]
    float* __restrict__ out_prec)          // [B,N]
{
    __shared__ float s_keys[5 * Wn];
    __shared__ float s_warp[32];
    __shared__ float s_bc[16];   // [0..4] key norms, [8..12] softplus(strength)
    __shared__ float s_a[Nn];    // sort keys, later alloc scatter target
    __shared__ int   s_idx[Nn];

    const int b = blockIdx.x;
    const int tid = threadIdx.x;
    const int lane = tid & 31;
    const int wid = tid >> 5;
    const int n = tid;

    // stage keys (read heads 0..3 then write head 4)
    if (tid < 4 * Wn) s_keys[tid] = read_keys[b * 4 * Wn + tid];
    else if (tid < 5 * Wn) s_keys[tid] = write_keys[b * Wn + (tid - 4 * Wn)];
    __syncthreads();

    if (tid < 5) {
        float s = 0.f;
#pragma unroll
        for (int w = 0; w < Wn; w++) { float k = s_keys[tid * Wn + w]; s += k * k; }
        s_bc[tid] = sqrtf(s + EPSF);
        float st = (tid < 4) ? read_str[b * 4 + tid] : write_str[b];
        s_bc[8 + tid] = softplusf(st);
    }

    // ---- usage (no shared dependency) ----
    float pu  = prev_usage[b * Nn + n];
    float wwp = prev_ww[b * Nn + n];
    float u = pu + (1.f - pu) * wwp;       // NW==1: ww == prev_write_weights
    float phi = 1.f;
#pragma unroll
    for (int r = 0; r < Rn; r++)
        phi *= 1.f - __ldg(&free_gate[b * Rn + r]) * prev_rw[((size_t)b * Rn + r) * Nn + n];
    float usage = u * phi;
    out_usage[b * Nn + n] = usage;

    __syncthreads();  // s_bc ready

    // ---- cosine content addressing for 5 heads ----
    float dot[5] = {0.f, 0.f, 0.f, 0.f, 0.f};
    float mn = 0.f;
    const float4* mrow = (const float4*)(memory + ((size_t)(b * Nn + n)) * Wn);
#pragma unroll 4
    for (int i = 0; i < Wn / 4; i++) {
        float4 m = mrow[i];
        mn += m.x * m.x + m.y * m.y + m.z * m.z + m.w * m.w;
#pragma unroll
        for (int h = 0; h < 5; h++) {
            const float* k = &s_keys[h * Wn + i * 4];
            dot[h] += m.x * k[0] + m.y * k[1] + m.z * k[2] + m.w * k[3];
        }
    }
    mn = sqrtf(mn + EPSF);

    float sharp[5];
#pragma unroll
    for (int h = 0; h < 5; h++) {
        float denom = s_bc[h] * mn + EPSF;
        sharp[h] = (dot[h] / denom) * s_bc[8 + h];
    }

    // softmax over N per head
    float wc = 0.f;
#pragma unroll
    for (int h = 0; h < 5; h++) {
        float M = block_rmax(sharp[h], s_warp, tid);
        float e = expf(sharp[h] - M);
        float S = block_rsum(e, s_warp, tid);
        float wv = e / S;
        if (h < 4) out_rw[((size_t)b * 4 + h) * Nn + n] = wv;
        else wc = wv;
    }

    // ---- allocation: hybrid bitonic sort (descending nonusage) ----
    float uc = EPSF + (1.f - EPSF) * usage;
    float nu = 1.f - uc;

    // k = 2..32: entirely in-warp (registers, zero barriers)
    float v = nu;
    int   ix = tid;
#pragma unroll
    for (int k = 2; k <= 32; k <<= 1) {
        bool desc = (tid & k) == 0;
#pragma unroll
        for (int j = k >> 1; j > 0; j >>= 1) bitonic_shfl(v, ix, j, desc, tid);
    }
    s_a[tid] = v;
    s_idx[tid] = ix;
    __syncthreads();

    // k = 64..1024: shared rounds for j>=32, register tail for j<=16
    for (int k = 64; k <= Nn; k <<= 1) {
        for (int j = k >> 1; j >= 32; j >>= 1) {
            int ixj = tid ^ j;
            if (ixj > tid) {
                float a = s_a[tid], c = s_a[ixj];
                bool descBlock = ((tid & k) == 0);
                bool doswap = descBlock ? (a < c) : (a > c);
                if (doswap) {
                    s_a[tid] = c; s_a[ixj] = a;
                    int t0 = s_idx[tid]; s_idx[tid] = s_idx[ixj]; s_idx[ixj] = t0;
                }
            }
            __syncthreads();
        }
        float vv = s_a[tid];
        int   ii = s_idx[tid];
        bool desc = (tid & k) == 0;
#pragma unroll
        for (int j = 16; j > 0; j >>= 1) bitonic_shfl(vv, ii, j, desc, tid);
        s_a[tid] = vv;
        s_idx[tid] = ii;
        __syncthreads();
    }

    float snu  = s_a[tid];
    int   sidx = s_idx[tid];
    float su   = 1.f - snu;   // sorted usage

    // ---- exclusive multiplicative scan, shuffle-based two-level ----
    float inc = su;
#pragma unroll
    for (int o = 1; o < 32; o <<= 1) {
        float t = __shfl_up_sync(0xffffffffu, inc, o);
        if (lane >= o) inc *= t;
    }
    if (lane == 31) s_warp[wid] = inc;
    __syncthreads();
    if (wid == 0) {
        float winc = s_warp[lane];
#pragma unroll
        for (int o = 1; o < 32; o <<= 1) {
            float t = __shfl_up_sync(0xffffffffu, winc, o);
            if (lane >= o) winc *= t;
        }
        float wexcl = __shfl_up_sync(0xffffffffu, winc, 1);
        s_warp[lane] = (lane == 0) ? 1.f : wexcl;
    }
    __syncthreads();
    float warp_excl = s_warp[wid];
    float lane_excl = __shfl_up_sync(0xffffffffu, inc, 1);
    float excl = warp_excl * ((lane == 0) ? 1.f : lane_excl);
    float salloc = snu * excl;

    __syncthreads();
    s_a[sidx] = salloc;       // scatter back to original order
    __syncthreads();
    float alloc = s_a[tid];

    // ---- write weights + precedence ----
    float ag = __ldg(&alloc_gate[b]);
    float wg = __ldg(&write_gate[b]);
    float wwv = wg * (ag * alloc + (1.f - ag) * wc);
    out_ww[b * Nn + n] = wwv;

    float wsum = block_rsum(wwv, s_warp, tid);
    out_prec[b * Nn + n] = (1.f - wsum) * __ldg(&prev_prec[b * Nn + n]) + wwv;
}

// ---------------------------------------------------------------------------
// Link update: link[b,i,j] = (1 - ww[i] - ww[j]) * prev_link + ww[i]*prev_prec[j]
// with zero diagonal. Pure HBM stream (512 MB); 8 rows per block so the
// ww[j]/prec[j] row vectors stay in registers (L2 traffic amortized).
// ---------------------------------------------------------------------------
constexpr int ROWS_PB = 8;
__global__ __launch_bounds__(256) void dnc_link_kernel(
    const float* __restrict__ prev_link,  // [B,1,N,N]
    const float* __restrict__ prev_prec,  // [B,1,N]
    const float* __restrict__ ww,         // [B,N] (new write weights)
    float* __restrict__ out_link)         // [B,1,N,N]
{
    const int blk = blockIdx.x;
    const int b  = blk / (Nn / ROWS_PB);
    const int i0 = (blk % (Nn / ROWS_PB)) * ROWS_PB;
    const int t  = threadIdx.x;
    const int j0 = t * 4;

    float4 Wj = __ldg((const float4*)(ww + (size_t)b * Nn) + t);
    float4 Pj = __ldg((const float4*)(prev_prec + (size_t)b * Nn) + t);

    // the 8 row weights ww[i0..i0+7], loaded once as two float4s
    float4 Wi0 = __ldg((const float4*)(ww + (size_t)b * Nn + i0));
    float4 Wi1 = __ldg((const float4*)(ww + (size_t)b * Nn + i0 + 4));
    float wi_arr[ROWS_PB] = {Wi0.x, Wi0.y, Wi0.z, Wi0.w, Wi1.x, Wi1.y, Wi1.z, Wi1.w};

    const float4* pl = (const float4*)(prev_link + ((size_t)b * Nn + i0) * Nn) + t;
    float4*       ol = (float4*)(out_link + ((size_t)b * Nn + i0) * Nn) + t;

    float4 L[ROWS_PB];
#pragma unroll
    for (int r = 0; r < ROWS_PB; r++) L[r] = pl[r * (Nn / 4)];

#pragma unroll
    for (int r = 0; r < ROWS_PB; r++) {
        int i = i0 + r;
        float wi = wi_arr[r];
        float ci = 1.f - wi;
        float4 o;
        o.x = (ci - Wj.x) * L[r].x + wi * Pj.x;
        o.y = (ci - Wj.y) * L[r].y + wi * Pj.y;
        o.z = (ci - Wj.z) * L[r].z + wi * Pj.z;
        o.w = (ci - Wj.w) * L[r].w + wi * Pj.w;
        int d = i - j0;
        if ((unsigned)d < 4u) ((float*)&o)[d] = 0.f;  // diagonal
        ol[r * (Nn / 4)] = o;
    }
}

// ---------------------------------------------------------------------------
// launch
// ---------------------------------------------------------------------------
extern "C" void kernel_launch(void* const* d_in, const int* in_sizes, int n_in,
                              void* d_out, int out_size) {
    const float* memory     = (const float*)d_in[0];
    const float* read_keys  = (const float*)d_in[1];
    const float* read_str   = (const float*)d_in[2];
    const float* write_keys = (const float*)d_in[3];
    const float* write_str  = (const float*)d_in[4];
    const float* free_gate  = (const float*)d_in[5];
    const float* alloc_gate = (const float*)d_in[6];
    const float* write_gate = (const float*)d_in[7];
    const float* prev_rw    = (const float*)d_in[8];
    const float* prev_ww    = (const float*)d_in[9];
    const float* prev_usage = (const float*)d_in[10];
    const float* prev_link  = (const float*)d_in[11];
    const float* prev_prec  = (const float*)d_in[12];

    float* out = (float*)d_out;
    float* out_rw    = out;                                   // [B,R,N]
    float* out_ww    = out_rw + (size_t)Bn * Rn * Nn;         // [B,1,N]
    float* out_usage = out_ww + (size_t)Bn * Nn;              // [B,N]
    float* out_link  = out_usage + (size_t)Bn * Nn;           // [B,1,N,N]
    float* out_prec  = out_link + (size_t)Bn * Nn * Nn;       // [B,1,N]

    dnc_batch_kernel<<<Bn, 1024>>>(
        memory, read_keys, read_str, write_keys, write_str,
        free_gate, alloc_gate, write_gate,
        prev_rw, prev_ww, prev_usage, prev_prec,
        out_rw, out_ww, out_usage, out_prec);

    dnc_link_kernel<<<(Bn * Nn) / ROWS_PB, 256>>>(
        prev_link, prev_prec, out_ww, out_link);
}

// round 8
// speedup vs baseline: 1.0683x; 1.0683x over previous
#include <cuda_runtime.h>
#include <cstddef>

// Problem constants (DNCMemory: B=64, N=1024, W=64, R=4, NW=1)
#define EPSF 1e-5f
constexpr int Bn = 64;
constexpr int Nn = 1024;
constexpr int Wn = 64;
constexpr int Rn = 4;

// Scratch for the split pipeline (device globals: no allocations allowed)
__device__ float g_wc[Bn * Nn];     // write-head content weights
__device__ float g_alloc[Bn * Nn];  // allocation weights

// ---------------------------------------------------------------------------
// reductions
// ---------------------------------------------------------------------------
__device__ __forceinline__ float warp_rsum(float v) {
#pragma unroll
    for (int o = 16; o > 0; o >>= 1) v += __shfl_xor_sync(0xffffffffu, v, o);
    return v;
}
__device__ __forceinline__ float warp_rmax(float v) {
#pragma unroll
    for (int o = 16; o > 0; o >>= 1) v = fmaxf(v, __shfl_xor_sync(0xffffffffu, v, o));
    return v;
}
__device__ __forceinline__ float block_rsum(float v, float* s_warp, int tid) {
    v = warp_rsum(v);
    if ((tid & 31) == 0) s_warp[tid >> 5] = v;
    __syncthreads();
    if (tid < 32) {
        float x = s_warp[tid];
        x = warp_rsum(x);
        if (tid == 0) s_warp[0] = x;
    }
    __syncthreads();
    float r = s_warp[0];
    __syncthreads();
    return r;
}
__device__ __forceinline__ float block_rmax(float v, float* s_warp, int tid) {
    v = warp_rmax(v);
    if ((tid & 31) == 0) s_warp[tid >> 5] = v;
    __syncthreads();
    if (tid < 32) {
        float x = s_warp[tid];
        x = warp_rmax(x);
        if (tid == 0) s_warp[0] = x;
    }
    __syncthreads();
    float r = s_warp[0];
    __syncthreads();
    return r;
}

__device__ __forceinline__ float softplusf(float x) {
    return fmaxf(x, 0.f) + log1pf(expf(-fabsf(x)));
}

// In-warp bitonic compare-exchange for stride j (j <= 16).
__device__ __forceinline__ void bitonic_shfl(float& v, int& ix, int j, bool desc, int tid) {
    float ov = __shfl_xor_sync(0xffffffffu, v, j);
    int   oi = __shfl_xor_sync(0xffffffffu, ix, j);
    bool am_lower = ((tid & j) == 0);
    float lowv = am_lower ? v : ov;
    float upv  = am_lower ? ov : v;
    bool sw = desc ? (lowv < upv) : (lowv > upv);
    if (sw) { v = ov; ix = oi; }
}

// ---------------------------------------------------------------------------
// Kernel 1: 128 blocks, two roles per batch, run concurrently.
//  role 0 (content): cosine addressing + softmax for 5 heads -> out_rw, g_wc
//  role 1 (alloc):   usage + bitonic sort + cumprod scan     -> out_usage, g_alloc
// ---------------------------------------------------------------------------
__global__ __launch_bounds__(1024, 1) void dnc_stage1_kernel(
    const float* __restrict__ memory,      // [B,N,W]
    const float* __restrict__ read_keys,   // [B,R,W]
    const float* __restrict__ read_str,    // [B,R]
    const float* __restrict__ write_keys,  // [B,1,W]
    const float* __restrict__ write_str,   // [B,1]
    const float* __restrict__ free_gate,   // [B,R]
    const float* __restrict__ prev_rw,     // [B,R,N]
    const float* __restrict__ prev_ww,     // [B,1,N]
    const float* __restrict__ prev_usage,  // [B,N]
    float* __restrict__ out_rw,            // [B,R,N]
    float* __restrict__ out_usage)         // [B,N]
{
    __shared__ float s_mem[5 * Wn];   // keys (content) — reused as sort array (alloc)
    __shared__ float s_warp[32];
    __shared__ float s_bc[16];
    __shared__ float s_a[Nn];
    __shared__ int   s_idx[Nn];

    const int b = blockIdx.x >> 1;
    const int role = blockIdx.x & 1;
    const int tid = threadIdx.x;
    const int lane = tid & 31;
    const int wid = tid >> 5;
    const int n = tid;

    if (role == 0) {
        // ======== content addressing ========
        if (tid < 4 * Wn) s_mem[tid] = read_keys[b * 4 * Wn + tid];
        else if (tid < 5 * Wn) s_mem[tid] = write_keys[b * Wn + (tid - 4 * Wn)];
        __syncthreads();

        if (tid < 5) {
            float s = 0.f;
#pragma unroll
            for (int w = 0; w < Wn; w++) { float k = s_mem[tid * Wn + w]; s += k * k; }
            s_bc[tid] = sqrtf(s + EPSF);
            float st = (tid < 4) ? read_str[b * 4 + tid] : write_str[b];
            s_bc[8 + tid] = softplusf(st);
        }
        __syncthreads();

        float dot[5] = {0.f, 0.f, 0.f, 0.f, 0.f};
        float mn = 0.f;
        const float4* mrow = (const float4*)(memory + ((size_t)(b * Nn + n)) * Wn);
#pragma unroll 4
        for (int i = 0; i < Wn / 4; i++) {
            float4 m = mrow[i];
            mn += m.x * m.x + m.y * m.y + m.z * m.z + m.w * m.w;
#pragma unroll
            for (int h = 0; h < 5; h++) {
                const float* k = &s_mem[h * Wn + i * 4];
                dot[h] += m.x * k[0] + m.y * k[1] + m.z * k[2] + m.w * k[3];
            }
        }
        mn = sqrtf(mn + EPSF);

        float sharp[5];
#pragma unroll
        for (int h = 0; h < 5; h++) {
            float denom = s_bc[h] * mn + EPSF;
            sharp[h] = (dot[h] / denom) * s_bc[8 + h];
        }

#pragma unroll
        for (int h = 0; h < 5; h++) {
            float M = block_rmax(sharp[h], s_warp, tid);
            float e = expf(sharp[h] - M);
            float S = block_rsum(e, s_warp, tid);
            float wv = e / S;
            if (h < 4) out_rw[((size_t)b * 4 + h) * Nn + n] = wv;
            else g_wc[b * Nn + n] = wv;
        }
    } else {
        // ======== usage + allocation ========
        float pu  = prev_usage[b * Nn + n];
        float wwp = prev_ww[b * Nn + n];
        float u = pu + (1.f - pu) * wwp;
        float phi = 1.f;
#pragma unroll
        for (int r = 0; r < Rn; r++)
            phi *= 1.f - __ldg(&free_gate[b * Rn + r]) * prev_rw[((size_t)b * Rn + r) * Nn + n];
        float usage = u * phi;
        out_usage[b * Nn + n] = usage;

        float uc = EPSF + (1.f - EPSF) * usage;
        float nu = 1.f - uc;

        // k = 2..32: in-warp bitonic (registers, no barriers)
        float v = nu;
        int   ix = tid;
#pragma unroll
        for (int k = 2; k <= 32; k <<= 1) {
            bool desc = (tid & k) == 0;
#pragma unroll
            for (int j = k >> 1; j > 0; j >>= 1) bitonic_shfl(v, ix, j, desc, tid);
        }
        s_a[tid] = v;
        s_idx[tid] = ix;
        __syncthreads();

        // k = 64..1024: shared rounds for j>=32, register tail for j<=16
        for (int k = 64; k <= Nn; k <<= 1) {
            for (int j = k >> 1; j >= 32; j >>= 1) {
                int ixj = tid ^ j;
                if (ixj > tid) {
                    float a = s_a[tid], c = s_a[ixj];
                    bool descBlock = ((tid & k) == 0);
                    bool doswap = descBlock ? (a < c) : (a > c);
                    if (doswap) {
                        s_a[tid] = c; s_a[ixj] = a;
                        int t0 = s_idx[tid]; s_idx[tid] = s_idx[ixj]; s_idx[ixj] = t0;
                    }
                }
                __syncthreads();
            }
            float vv = s_a[tid];
            int   ii = s_idx[tid];
            bool desc = (tid & k) == 0;
#pragma unroll
            for (int j = 16; j > 0; j >>= 1) bitonic_shfl(vv, ii, j, desc, tid);
            s_a[tid] = vv;
            s_idx[tid] = ii;
            __syncthreads();
        }

        float snu  = s_a[tid];
        int   sidx = s_idx[tid];
        float su   = 1.f - snu;

        // exclusive multiplicative scan (shuffle two-level)
        float inc = su;
#pragma unroll
        for (int o = 1; o < 32; o <<= 1) {
            float t = __shfl_up_sync(0xffffffffu, inc, o);
            if (lane >= o) inc *= t;
        }
        if (lane == 31) s_warp[wid] = inc;
        __syncthreads();
        if (wid == 0) {
            float winc = s_warp[lane];
#pragma unroll
            for (int o = 1; o < 32; o <<= 1) {
                float t = __shfl_up_sync(0xffffffffu, winc, o);
                if (lane >= o) winc *= t;
            }
            float wexcl = __shfl_up_sync(0xffffffffu, winc, 1);
            s_warp[lane] = (lane == 0) ? 1.f : wexcl;
        }
        __syncthreads();
        float warp_excl = s_warp[wid];
        float lane_excl = __shfl_up_sync(0xffffffffu, inc, 1);
        float excl = warp_excl * ((lane == 0) ? 1.f : lane_excl);
        float salloc = snu * excl;

        __syncthreads();
        s_a[sidx] = salloc;
        __syncthreads();
        g_alloc[b * Nn + tid] = s_a[tid];
    }
}

// ---------------------------------------------------------------------------
// Kernel 2: combine -> write weights + precedence. 64 blocks x 1024 threads.
// ---------------------------------------------------------------------------
__global__ __launch_bounds__(1024, 1) void dnc_combine_kernel(
    const float* __restrict__ alloc_gate,  // [B,1]
    const float* __restrict__ write_gate,  // [B,1]
    const float* __restrict__ prev_prec,   // [B,1,N]
    float* __restrict__ out_ww,            // [B,N]
    float* __restrict__ out_prec)          // [B,N]
{
    __shared__ float s_warp[32];
    const int b = blockIdx.x;
    const int tid = threadIdx.x;

    float ag = __ldg(&alloc_gate[b]);
    float wg = __ldg(&write_gate[b]);
    float alloc = g_alloc[b * Nn + tid];
    float wc    = g_wc[b * Nn + tid];
    float wwv = wg * (ag * alloc + (1.f - ag) * wc);
    out_ww[b * Nn + tid] = wwv;

    float wsum = block_rsum(wwv, s_warp, tid);
    out_prec[b * Nn + tid] = (1.f - wsum) * __ldg(&prev_prec[b * Nn + tid]) + wwv;
}

// ---------------------------------------------------------------------------
// Kernel 3: link update. Streaming loads/stores (data touched exactly once).
// ---------------------------------------------------------------------------
constexpr int ROWS_PB = 8;
__global__ __launch_bounds__(256) void dnc_link_kernel(
    const float* __restrict__ prev_link,  // [B,1,N,N]
    const float* __restrict__ prev_prec,  // [B,1,N]
    const float* __restrict__ ww,         // [B,N]
    float* __restrict__ out_link)         // [B,1,N,N]
{
    const int blk = blockIdx.x;
    const int b  = blk / (Nn / ROWS_PB);
    const int i0 = (blk % (Nn / ROWS_PB)) * ROWS_PB;
    const int t  = threadIdx.x;
    const int j0 = t * 4;

    float4 Wj = __ldg((const float4*)(ww + (size_t)b * Nn) + t);
    float4 Pj = __ldg((const float4*)(prev_prec + (size_t)b * Nn) + t);

    float4 Wi0 = __ldg((const float4*)(ww + (size_t)b * Nn + i0));
    float4 Wi1 = __ldg((const float4*)(ww + (size_t)b * Nn + i0 + 4));
    float wi_arr[ROWS_PB] = {Wi0.x, Wi0.y, Wi0.z, Wi0.w, Wi1.x, Wi1.y, Wi1.z, Wi1.w};

    const float4* pl = (const float4*)(prev_link + ((size_t)b * Nn + i0) * Nn) + t;
    float4*       ol = (float4*)(out_link + ((size_t)b * Nn + i0) * Nn) + t;

    float4 L[ROWS_PB];
#pragma unroll
    for (int r = 0; r < ROWS_PB; r++) L[r] = __ldcs(pl + r * (Nn / 4));  // evict-first

#pragma unroll
    for (int r = 0; r < ROWS_PB; r++) {
        int i = i0 + r;
        float wi = wi_arr[r];
        float ci = 1.f - wi;
        float4 o;
        o.x = (ci - Wj.x) * L[r].x + wi * Pj.x;
        o.y = (ci - Wj.y) * L[r].y + wi * Pj.y;
        o.z = (ci - Wj.z) * L[r].z + wi * Pj.z;
        o.w = (ci - Wj.w) * L[r].w + wi * Pj.w;
        int d = i - j0;
        if ((unsigned)d < 4u) ((float*)&o)[d] = 0.f;  // diagonal
        __stcs(ol + r * (Nn / 4), o);                 // streaming store
    }
}

// ---------------------------------------------------------------------------
// launch
// ---------------------------------------------------------------------------
extern "C" void kernel_launch(void* const* d_in, const int* in_sizes, int n_in,
                              void* d_out, int out_size) {
    const float* memory     = (const float*)d_in[0];
    const float* read_keys  = (const float*)d_in[1];
    const float* read_str   = (const float*)d_in[2];
    const float* write_keys = (const float*)d_in[3];
    const float* write_str  = (const float*)d_in[4];
    const float* free_gate  = (const float*)d_in[5];
    const float* alloc_gate = (const float*)d_in[6];
    const float* write_gate = (const float*)d_in[7];
    const float* prev_rw    = (const float*)d_in[8];
    const float* prev_ww    = (const float*)d_in[9];
    const float* prev_usage = (const float*)d_in[10];
    const float* prev_link  = (const float*)d_in[11];
    const float* prev_prec  = (const float*)d_in[12];

    float* out = (float*)d_out;
    float* out_rw    = out;                                   // [B,R,N]
    float* out_ww    = out_rw + (size_t)Bn * Rn * Nn;         // [B,1,N]
    float* out_usage = out_ww + (size_t)Bn * Nn;              // [B,N]
    float* out_link  = out_usage + (size_t)Bn * Nn;           // [B,1,N,N]
    float* out_prec  = out_link + (size_t)Bn * Nn * Nn;       // [B,1,N]

    dnc_stage1_kernel<<<2 * Bn, 1024>>>(
        memory, read_keys, read_str, write_keys, write_str,
        free_gate, prev_rw, prev_ww, prev_usage,
        out_rw, out_usage);

    dnc_combine_kernel<<<Bn, 1024>>>(
        alloc_gate, write_gate, prev_prec, out_ww, out_prec);

    dnc_link_kernel<<<(Bn * Nn) / ROWS_PB, 256>>>(
        prev_link, prev_prec, out_ww, out_link);
}

// round 11
// speedup vs baseline: 1.0876x; 1.0181x over previous
#include <cuda_runtime.h>
#include <cstddef>

// Problem constants (DNCMemory: B=64, N=1024, W=64, R=4, NW=1)
#define EPSF 1e-5f
constexpr int Bn = 64;
constexpr int Nn = 1024;
constexpr int Wn = 64;
constexpr int Rn = 4;

// Scratch (device globals: no allocations allowed)
__device__ float g_wc[Bn * Nn];     // write-head content weights
__device__ float g_alloc[Bn * Nn];  // allocation weights
__device__ float g_asum[Bn];        // sum of allocation weights per batch

// ---------------------------------------------------------------------------
// reductions
// ---------------------------------------------------------------------------
__device__ __forceinline__ float warp_rsum(float v) {
#pragma unroll
    for (int o = 16; o > 0; o >>= 1) v += __shfl_xor_sync(0xffffffffu, v, o);
    return v;
}
__device__ __forceinline__ float warp_rmax(float v) {
#pragma unroll
    for (int o = 16; o > 0; o >>= 1) v = fmaxf(v, __shfl_xor_sync(0xffffffffu, v, o));
    return v;
}
__device__ __forceinline__ float block_rsum(float v, float* s_warp, int tid) {
    v = warp_rsum(v);
    if ((tid & 31) == 0) s_warp[tid >> 5] = v;
    __syncthreads();
    if (tid < 32) {
        float x = s_warp[tid];
        x = warp_rsum(x);
        if (tid == 0) s_warp[0] = x;
    }
    __syncthreads();
    float r = s_warp[0];
    __syncthreads();
    return r;
}

__device__ __forceinline__ float softplusf(float x) {
    return fmaxf(x, 0.f) + log1pf(expf(-fabsf(x)));
}

// In-warp bitonic compare-exchange for stride j (j <= 16).
__device__ __forceinline__ void bitonic_shfl(float& v, int& ix, int j, bool desc, int tid) {
    float ov = __shfl_xor_sync(0xffffffffu, v, j);
    int   oi = __shfl_xor_sync(0xffffffffu, ix, j);
    bool am_lower = ((tid & j) == 0);
    float lowv = am_lower ? v : ov;
    float upv  = am_lower ? ov : v;
    bool sw = desc ? (lowv < upv) : (lowv > upv);
    if (sw) { v = ov; ix = oi; }
}

// ---------------------------------------------------------------------------
// Kernel 1: 128 blocks, two roles per batch, run concurrently.
//  role 0 (content): cosine addressing + BATCHED softmax (4 barriers, not 30)
//  role 1 (alloc):   usage + bitonic sort + cumprod scan + sum_alloc
// ---------------------------------------------------------------------------
__global__ __launch_bounds__(1024, 1) void dnc_stage1_kernel(
    const float* __restrict__ memory,      // [B,N,W]
    const float* __restrict__ read_keys,   // [B,R,W]
    const float* __restrict__ read_str,    // [B,R]
    const float* __restrict__ write_keys,  // [B,1,W]
    const float* __restrict__ write_str,   // [B,1]
    const float* __restrict__ free_gate,   // [B,R]
    const float* __restrict__ prev_rw,     // [B,R,N]
    const float* __restrict__ prev_ww,     // [B,1,N]
    const float* __restrict__ prev_usage,  // [B,N]
    float* __restrict__ out_rw,            // [B,R,N]
    float* __restrict__ out_usage)         // [B,N]
{
    __shared__ float s_mem[5 * Wn];
    __shared__ float s_warp[32];
    __shared__ float s_bc[16];
    __shared__ float s_red[5 * 32];   // batched-reduction staging
    __shared__ float s_resM[8];       // per-head block max
    __shared__ float s_resS[8];       // per-head block sum
    __shared__ float s_a[Nn];
    __shared__ int   s_idx[Nn];

    const int b = blockIdx.x >> 1;
    const int role = blockIdx.x & 1;
    const int tid = threadIdx.x;
    const int lane = tid & 31;
    const int wid = tid >> 5;
    const int n = tid;

    if (role == 0) {
        // ======== content addressing ========
        if (tid < 4 * Wn) s_mem[tid] = read_keys[b * 4 * Wn + tid];
        else if (tid < 5 * Wn) s_mem[tid] = write_keys[b * Wn + (tid - 4 * Wn)];
        __syncthreads();

        if (tid < 5) {
            float s = 0.f;
#pragma unroll
            for (int w = 0; w < Wn; w++) { float k = s_mem[tid * Wn + w]; s += k * k; }
            s_bc[tid] = sqrtf(s + EPSF);
            float st = (tid < 4) ? read_str[b * 4 + tid] : write_str[b];
            s_bc[8 + tid] = softplusf(st);
        }
        __syncthreads();

        float dot[5] = {0.f, 0.f, 0.f, 0.f, 0.f};
        float mn = 0.f;
        const float4* mrow = (const float4*)(memory + ((size_t)(b * Nn + n)) * Wn);
#pragma unroll 4
        for (int i = 0; i < Wn / 4; i++) {
            float4 m = mrow[i];
            mn += m.x * m.x + m.y * m.y + m.z * m.z + m.w * m.w;
#pragma unroll
            for (int h = 0; h < 5; h++) {
                const float* k = &s_mem[h * Wn + i * 4];
                dot[h] += m.x * k[0] + m.y * k[1] + m.z * k[2] + m.w * k[3];
            }
        }
        mn = sqrtf(mn + EPSF);

        float sharp[5];
#pragma unroll
        for (int h = 0; h < 5; h++) {
            float denom = s_bc[h] * mn + EPSF;
            sharp[h] = (dot[h] / denom) * s_bc[8 + h];
        }

        // ---- batched softmax: all 5 maxes, then all 5 sums (4 barriers) ----
#pragma unroll
        for (int h = 0; h < 5; h++) {
            float m = warp_rmax(sharp[h]);
            if (lane == 0) s_red[h * 32 + wid] = m;
        }
        __syncthreads();
        if (wid < 5) {
            float x = warp_rmax(s_red[wid * 32 + lane]);
            if (lane == 0) s_resM[wid] = x;
        }
        __syncthreads();

        float e[5];
#pragma unroll
        for (int h = 0; h < 5; h++) {
            e[h] = expf(sharp[h] - s_resM[h]);
            float s = warp_rsum(e[h]);
            if (lane == 0) s_red[h * 32 + wid] = s;
        }
        __syncthreads();
        if (wid < 5) {
            float x = warp_rsum(s_red[wid * 32 + lane]);
            if (lane == 0) s_resS[wid] = x;
        }
        __syncthreads();

#pragma unroll
        for (int h = 0; h < 5; h++) {
            float wv = e[h] / s_resS[h];
            if (h < 4) out_rw[((size_t)b * 4 + h) * Nn + n] = wv;
            else g_wc[b * Nn + n] = wv;
        }
    } else {
        // ======== usage + allocation ========
        float pu  = prev_usage[b * Nn + n];
        float wwp = prev_ww[b * Nn + n];
        float u = pu + (1.f - pu) * wwp;
        float phi = 1.f;
#pragma unroll
        for (int r = 0; r < Rn; r++)
            phi *= 1.f - __ldg(&free_gate[b * Rn + r]) * prev_rw[((size_t)b * Rn + r) * Nn + n];
        float usage = u * phi;
        out_usage[b * Nn + n] = usage;

        float uc = EPSF + (1.f - EPSF) * usage;
        float nu = 1.f - uc;

        // k = 2..32: in-warp bitonic (registers, no barriers)
        float v = nu;
        int   ix = tid;
#pragma unroll
        for (int k = 2; k <= 32; k <<= 1) {
            bool desc = (tid & k) == 0;
#pragma unroll
            for (int j = k >> 1; j > 0; j >>= 1) bitonic_shfl(v, ix, j, desc, tid);
        }
        s_a[tid] = v;
        s_idx[tid] = ix;
        __syncthreads();

        // k = 64..1024: shared rounds for j>=32, register tail for j<=16
        for (int k = 64; k <= Nn; k <<= 1) {
            for (int j = k >> 1; j >= 32; j >>= 1) {
                int ixj = tid ^ j;
                if (ixj > tid) {
                    float a = s_a[tid], c = s_a[ixj];
                    bool descBlock = ((tid & k) == 0);
                    bool doswap = descBlock ? (a < c) : (a > c);
                    if (doswap) {
                        s_a[tid] = c; s_a[ixj] = a;
                        int t0 = s_idx[tid]; s_idx[tid] = s_idx[ixj]; s_idx[ixj] = t0;
                    }
                }
                __syncthreads();
            }
            float vv = s_a[tid];
            int   ii = s_idx[tid];
            bool desc = (tid & k) == 0;
#pragma unroll
            for (int j = 16; j > 0; j >>= 1) bitonic_shfl(vv, ii, j, desc, tid);
            s_a[tid] = vv;
            s_idx[tid] = ii;
            __syncthreads();
        }

        float snu  = s_a[tid];
        int   sidx = s_idx[tid];
        float su   = 1.f - snu;

        // exclusive multiplicative scan (shuffle two-level)
        float inc = su;
#pragma unroll
        for (int o = 1; o < 32; o <<= 1) {
            float t = __shfl_up_sync(0xffffffffu, inc, o);
            if (lane >= o) inc *= t;
        }
        if (lane == 31) s_warp[wid] = inc;
        __syncthreads();
        if (wid == 0) {
            float winc = s_warp[lane];
#pragma unroll
            for (int o = 1; o < 32; o <<= 1) {
                float t = __shfl_up_sync(0xffffffffu, winc, o);
                if (lane >= o) winc *= t;
            }
            float wexcl = __shfl_up_sync(0xffffffffu, winc, 1);
            s_warp[lane] = (lane == 0) ? 1.f : wexcl;
        }
        __syncthreads();
        float warp_excl = s_warp[wid];
        float lane_excl = __shfl_up_sync(0xffffffffu, inc, 1);
        float excl = warp_excl * ((lane == 0) ? 1.f : lane_excl);
        float salloc = snu * excl;

        __syncthreads();
        s_a[sidx] = salloc;
        __syncthreads();
        g_alloc[b * Nn + tid] = s_a[tid];

        // sum of allocation weights (for wsum in the link kernel)
        float ssum = block_rsum(salloc, s_warp, tid);
        if (tid == 0) g_asum[b] = ssum;
    }
}

// ---------------------------------------------------------------------------
// Kernel 2: link update + inline write-weight combine + ww/prec outputs.
//   ww_j = wg*(ag*alloc_j + (1-ag)*wc_j)   (from scratch buffers)
//   wsum = wg*(ag*sum_alloc + (1-ag))      (sum of softmax == 1 analytically)
// 16 rows per block, processed as two 8-row halves for register pressure.
// ---------------------------------------------------------------------------
constexpr int ROWS_PB = 16;
constexpr int HALF = 8;
__global__ __launch_bounds__(256) void dnc_link_kernel(
    const float* __restrict__ prev_link,  // [B,1,N,N]
    const float* __restrict__ prev_prec,  // [B,1,N]
    const float* __restrict__ alloc_gate, // [B,1]
    const float* __restrict__ write_gate, // [B,1]
    float* __restrict__ out_link,         // [B,1,N,N]
    float* __restrict__ out_ww,           // [B,N]
    float* __restrict__ out_prec)         // [B,N]
{
    const int blk = blockIdx.x;
    const int b  = blk / (Nn / ROWS_PB);
    const int i0 = (blk % (Nn / ROWS_PB)) * ROWS_PB;
    const int t  = threadIdx.x;
    const int j0 = t * 4;

    const float ag = __ldg(&alloc_gate[b]);
    const float wg = __ldg(&write_gate[b]);
    const float cg = wg * (1.f - ag);
    const float gg = wg * ag;

    float4 Aj = __ldg((const float4*)(g_alloc + (size_t)b * Nn) + t);
    float4 Cj = __ldg((const float4*)(g_wc + (size_t)b * Nn) + t);
    float4 Wj;
    Wj.x = gg * Aj.x + cg * Cj.x;
    Wj.y = gg * Aj.y + cg * Cj.y;
    Wj.z = gg * Aj.z + cg * Cj.z;
    Wj.w = gg * Aj.w + cg * Cj.w;
    float4 Pj = __ldg((const float4*)(prev_prec + (size_t)b * Nn) + t);

    // row weights ww[i0..i0+15]
    float wi_arr[ROWS_PB];
#pragma unroll
    for (int q = 0; q < ROWS_PB / 4; q++) {
        float4 Ai = __ldg((const float4*)(g_alloc + (size_t)b * Nn + i0 + q * 4));
        float4 Ci = __ldg((const float4*)(g_wc + (size_t)b * Nn + i0 + q * 4));
        wi_arr[q * 4 + 0] = gg * Ai.x + cg * Ci.x;
        wi_arr[q * 4 + 1] = gg * Ai.y + cg * Ci.y;
        wi_arr[q * 4 + 2] = gg * Ai.z + cg * Ci.z;
        wi_arr[q * 4 + 3] = gg * Ai.w + cg * Ci.w;
    }

    const float4* pl = (const float4*)(prev_link + ((size_t)b * Nn + i0) * Nn) + t;
    float4*       ol = (float4*)(out_link + ((size_t)b * Nn + i0) * Nn) + t;

#pragma unroll
    for (int half = 0; half < 2; half++) {
        float4 L[HALF];
#pragma unroll
        for (int r = 0; r < HALF; r++)
            L[r] = __ldcs(pl + (half * HALF + r) * (Nn / 4));
#pragma unroll
        for (int r = 0; r < HALF; r++) {
            int rr = half * HALF + r;
            int i = i0 + rr;
            float wi = wi_arr[rr];
            float ci = 1.f - wi;
            float4 o;
            o.x = (ci - Wj.x) * L[r].x + wi * Pj.x;
            o.y = (ci - Wj.y) * L[r].y + wi * Pj.y;
            o.z = (ci - Wj.z) * L[r].z + wi * Pj.z;
            o.w = (ci - Wj.w) * L[r].w + wi * Pj.w;
            int d = i - j0;
            if ((unsigned)d < 4u) ((float*)&o)[d] = 0.f;  // diagonal
            __stcs(ol + rr * (Nn / 4), o);
        }
    }

    // one block per batch also emits ww and precedence (t spans all 1024 j)
    if (i0 == 0) {
        float wsum = wg * (ag * __ldg(&g_asum[b]) + (1.f - ag));
        float om = 1.f - wsum;
        ((float4*)(out_ww + (size_t)b * Nn))[t] = Wj;
        float4 pr;
        pr.x = om * Pj.x + Wj.x;
        pr.y = om * Pj.y + Wj.y;
        pr.z = om * Pj.z + Wj.z;
        pr.w = om * Pj.w + Wj.w;
        ((float4*)(out_prec + (size_t)b * Nn))[t] = pr;
    }
}

// ---------------------------------------------------------------------------
// launch
// ---------------------------------------------------------------------------
extern "C" void kernel_launch(void* const* d_in, const int* in_sizes, int n_in,
                              void* d_out, int out_size) {
    const float* memory     = (const float*)d_in[0];
    const float* read_keys  = (const float*)d_in[1];
    const float* read_str   = (const float*)d_in[2];
    const float* write_keys = (const float*)d_in[3];
    const float* write_str  = (const float*)d_in[4];
    const float* free_gate  = (const float*)d_in[5];
    const float* alloc_gate = (const float*)d_in[6];
    const float* write_gate = (const float*)d_in[7];
    const float* prev_rw    = (const float*)d_in[8];
    const float* prev_ww    = (const float*)d_in[9];
    const float* prev_usage = (const float*)d_in[10];
    const float* prev_link  = (const float*)d_in[11];
    const float* prev_prec  = (const float*)d_in[12];

    float* out = (float*)d_out;
    float* out_rw    = out;                                   // [B,R,N]
    float* out_ww    = out_rw + (size_t)Bn * Rn * Nn;         // [B,1,N]
    float* out_usage = out_ww + (size_t)Bn * Nn;              // [B,N]
    float* out_link  = out_usage + (size_t)Bn * Nn;           // [B,1,N,N]
    float* out_prec  = out_link + (size_t)Bn * Nn * Nn;       // [B,1,N]

    dnc_stage1_kernel<<<2 * Bn, 1024>>>(
        memory, read_keys, read_str, write_keys, write_str,
        free_gate, prev_rw, prev_ww, prev_usage,
        out_rw, out_usage);

    dnc_link_kernel<<<(Bn * Nn) / ROWS_PB, 256>>>(
        prev_link, prev_prec, alloc_gate, write_gate,
        out_link, out_ww, out_prec);
}

// round 14
// speedup vs baseline: 1.0947x; 1.0065x over previous
#include <cuda_runtime.h>
#include <cstddef>
#include <cstdint>

// Problem constants (DNCMemory: B=64, N=1024, W=64, R=4, NW=1)
#define EPSF 1e-5f
constexpr int Bn = 64;
constexpr int Nn = 1024;
constexpr int Wn = 64;
constexpr int Rn = 4;

// Scratch (device globals: no allocations allowed)
__device__ float g_wc[Bn * Nn];     // write-head content weights
__device__ float g_alloc[Bn * Nn];  // allocation weights
__device__ float g_asum[Bn];        // sum of allocation weights per batch

// ---------------------------------------------------------------------------
// reductions
// ---------------------------------------------------------------------------
__device__ __forceinline__ float warp_rsum(float v) {
#pragma unroll
    for (int o = 16; o > 0; o >>= 1) v += __shfl_xor_sync(0xffffffffu, v, o);
    return v;
}
__device__ __forceinline__ float warp_rmax(float v) {
#pragma unroll
    for (int o = 16; o > 0; o >>= 1) v = fmaxf(v, __shfl_xor_sync(0xffffffffu, v, o));
    return v;
}
__device__ __forceinline__ float block_rsum(float v, float* s_warp, int tid) {
    v = warp_rsum(v);
    if ((tid & 31) == 0) s_warp[tid >> 5] = v;
    __syncthreads();
    if (tid < 32) {
        float x = s_warp[tid];
        x = warp_rsum(x);
        if (tid == 0) s_warp[0] = x;
    }
    __syncthreads();
    float r = s_warp[0];
    __syncthreads();
    return r;
}

__device__ __forceinline__ float softplusf(float x) {
    return fmaxf(x, 0.f) + log1pf(expf(-fabsf(x)));
}

// In-warp bitonic compare-exchange on packed 64-bit keys (stride j <= 16).
// Descending regions keep larger keys first. Strict compare; tie-break is
// embedded in the low word of the key, so ordering is exact and stable.
__device__ __forceinline__ void bitonic_shfl_u64(unsigned long long& k, int j, bool desc, int tid) {
    unsigned int lo = (unsigned int)k, hi = (unsigned int)(k >> 32);
    unsigned int olo = __shfl_xor_sync(0xffffffffu, lo, j);
    unsigned int ohi = __shfl_xor_sync(0xffffffffu, hi, j);
    unsigned long long ok = ((unsigned long long)ohi << 32) | olo;
    bool am_lower = ((tid & j) == 0);
    unsigned long long lowk = am_lower ? k : ok;
    unsigned long long upk  = am_lower ? ok : k;
    bool sw = desc ? (lowk < upk) : (lowk > upk);
    if (sw) k = ok;
}

// ---------------------------------------------------------------------------
// Kernel 1: 128 blocks, two roles per batch, run concurrently.
//  role 0 (content): cosine addressing + BATCHED softmax (4 barriers)
//  role 1 (alloc):   usage + packed-key bitonic sort + cumprod scan + sum
// ---------------------------------------------------------------------------
__global__ __launch_bounds__(1024, 1) void dnc_stage1_kernel(
    const float* __restrict__ memory,      // [B,N,W]
    const float* __restrict__ read_keys,   // [B,R,W]
    const float* __restrict__ read_str,    // [B,R]
    const float* __restrict__ write_keys,  // [B,1,W]
    const float* __restrict__ write_str,   // [B,1]
    const float* __restrict__ free_gate,   // [B,R]
    const float* __restrict__ prev_rw,     // [B,R,N]
    const float* __restrict__ prev_ww,     // [B,1,N]
    const float* __restrict__ prev_usage,  // [B,N]
    float* __restrict__ out_rw,            // [B,R,N]
    float* __restrict__ out_usage)         // [B,N]
{
    __shared__ float s_mem[5 * Wn];
    __shared__ float s_warp[32];
    __shared__ float s_bc[16];
    __shared__ float s_red[5 * 32];   // batched-reduction staging
    __shared__ float s_resM[8];       // per-head block max
    __shared__ float s_resS[8];       // per-head block sum
    __shared__ unsigned long long s_key[Nn];  // packed sort keys
    __shared__ float s_a[Nn];                 // alloc scatter target

    const int b = blockIdx.x >> 1;
    const int role = blockIdx.x & 1;
    const int tid = threadIdx.x;
    const int lane = tid & 31;
    const int wid = tid >> 5;
    const int n = tid;

    if (role == 0) {
        // ======== content addressing ========
        if (tid < 4 * Wn) s_mem[tid] = read_keys[b * 4 * Wn + tid];
        else if (tid < 5 * Wn) s_mem[tid] = write_keys[b * Wn + (tid - 4 * Wn)];
        __syncthreads();

        if (tid < 5) {
            float s = 0.f;
#pragma unroll
            for (int w = 0; w < Wn; w++) { float k = s_mem[tid * Wn + w]; s += k * k; }
            s_bc[tid] = sqrtf(s + EPSF);
            float st = (tid < 4) ? read_str[b * 4 + tid] : write_str[b];
            s_bc[8 + tid] = softplusf(st);
        }
        __syncthreads();

        float dot[5] = {0.f, 0.f, 0.f, 0.f, 0.f};
        float mn = 0.f;
        const float4* mrow = (const float4*)(memory + ((size_t)(b * Nn + n)) * Wn);
#pragma unroll 4
        for (int i = 0; i < Wn / 4; i++) {
            float4 m = mrow[i];
            mn += m.x * m.x + m.y * m.y + m.z * m.z + m.w * m.w;
#pragma unroll
            for (int h = 0; h < 5; h++) {
                const float* k = &s_mem[h * Wn + i * 4];
                dot[h] += m.x * k[0] + m.y * k[1] + m.z * k[2] + m.w * k[3];
            }
        }
        mn = sqrtf(mn + EPSF);

        float sharp[5];
#pragma unroll
        for (int h = 0; h < 5; h++) {
            float denom = s_bc[h] * mn + EPSF;
            sharp[h] = (dot[h] / denom) * s_bc[8 + h];
        }

        // ---- batched softmax: all 5 maxes, then all 5 sums (4 barriers) ----
#pragma unroll
        for (int h = 0; h < 5; h++) {
            float m = warp_rmax(sharp[h]);
            if (lane == 0) s_red[h * 32 + wid] = m;
        }
        __syncthreads();
        if (wid < 5) {
            float x = warp_rmax(s_red[wid * 32 + lane]);
            if (lane == 0) s_resM[wid] = x;
        }
        __syncthreads();

        float e[5];
#pragma unroll
        for (int h = 0; h < 5; h++) {
            e[h] = expf(sharp[h] - s_resM[h]);
            float s = warp_rsum(e[h]);
            if (lane == 0) s_red[h * 32 + wid] = s;
        }
        __syncthreads();
        if (wid < 5) {
            float x = warp_rsum(s_red[wid * 32 + lane]);
            if (lane == 0) s_resS[wid] = x;
        }
        __syncthreads();

#pragma unroll
        for (int h = 0; h < 5; h++) {
            float wv = e[h] / s_resS[h];
            if (h < 4) out_rw[((size_t)b * 4 + h) * Nn + n] = wv;
            else g_wc[b * Nn + n] = wv;
        }
    } else {
        // ======== usage + allocation ========
        float pu  = prev_usage[b * Nn + n];
        float wwp = prev_ww[b * Nn + n];
        float u = pu + (1.f - pu) * wwp;
        float phi = 1.f;
#pragma unroll
        for (int r = 0; r < Rn; r++)
            phi *= 1.f - __ldg(&free_gate[b * Rn + r]) * prev_rw[((size_t)b * Rn + r) * Nn + n];
        float usage = u * phi;
        out_usage[b * Nn + n] = usage;

        float uc = EPSF + (1.f - EPSF) * usage;
        float nu = 1.f - uc;   // >= 0, so float bits are order-isomorphic

        // packed key: value bits in high word, stable tie-break in low word
        // (equal nu -> smaller original index sorts first in descending order)
        unsigned long long key =
            ((unsigned long long)__float_as_uint(nu) << 32) |
            (unsigned int)(Nn - 1 - tid);

        // k = 2..32: in-warp bitonic (registers, no barriers)
#pragma unroll
        for (int k = 2; k <= 32; k <<= 1) {
            bool desc = (tid & k) == 0;
#pragma unroll
            for (int j = k >> 1; j > 0; j >>= 1) bitonic_shfl_u64(key, j, desc, tid);
        }
        s_key[tid] = key;
        __syncthreads();

        // k = 64..1024: shared rounds for j>=32, register tail for j<=16
        for (int k = 64; k <= Nn; k <<= 1) {
            for (int j = k >> 1; j >= 32; j >>= 1) {
                int ixj = tid ^ j;
                if (ixj > tid) {
                    unsigned long long a = s_key[tid], c = s_key[ixj];
                    bool descBlock = ((tid & k) == 0);
                    bool doswap = descBlock ? (a < c) : (a > c);
                    if (doswap) { s_key[tid] = c; s_key[ixj] = a; }
                }
                __syncthreads();
            }
            unsigned long long kk = s_key[tid];
            bool desc = (tid & k) == 0;
#pragma unroll
            for (int j = 16; j > 0; j >>= 1) bitonic_shfl_u64(kk, j, desc, tid);
            s_key[tid] = kk;
            __syncthreads();
        }

        unsigned long long kfin = s_key[tid];
        float snu = __uint_as_float((unsigned int)(kfin >> 32));
        int   sidx = Nn - 1 - (int)(unsigned int)(kfin & 0xffffffffu);
        float su  = 1.f - snu;

        // exclusive multiplicative scan (shuffle two-level)
        float inc = su;
#pragma unroll
        for (int o = 1; o < 32; o <<= 1) {
            float t = __shfl_up_sync(0xffffffffu, inc, o);
            if (lane >= o) inc *= t;
        }
        if (lane == 31) s_warp[wid] = inc;
        __syncthreads();
        if (wid == 0) {
            float winc = s_warp[lane];
#pragma unroll
            for (int o = 1; o < 32; o <<= 1) {
                float t = __shfl_up_sync(0xffffffffu, winc, o);
                if (lane >= o) winc *= t;
            }
            float wexcl = __shfl_up_sync(0xffffffffu, winc, 1);
            s_warp[lane] = (lane == 0) ? 1.f : wexcl;
        }
        __syncthreads();
        float warp_excl = s_warp[wid];
        float lane_excl = __shfl_up_sync(0xffffffffu, inc, 1);
        float excl = warp_excl * ((lane == 0) ? 1.f : lane_excl);
        float salloc = snu * excl;

        s_a[sidx] = salloc;        // scatter back to original order
        __syncthreads();
        g_alloc[b * Nn + tid] = s_a[tid];

        // sum of allocation weights (for wsum in the link kernel)
        float ssum = block_rsum(salloc, s_warp, tid);
        if (tid == 0) g_asum[b] = ssum;
    }
}

// ---------------------------------------------------------------------------
// Kernel 2: link update + inline write-weight combine + ww/prec outputs.
//   ww_j = wg*(ag*alloc_j + (1-ag)*wc_j)   (from scratch buffers)
//   wsum = wg*(ag*sum_alloc + (1-ag))      (sum of softmax == 1 analytically)
// 8 rows per block (measured best: occ 63.5%, DRAM 80.8%).
// ---------------------------------------------------------------------------
constexpr int ROWS_PB = 8;
__global__ __launch_bounds__(256) void dnc_link_kernel(
    const float* __restrict__ prev_link,  // [B,1,N,N]
    const float* __restrict__ prev_prec,  // [B,1,N]
    const float* __restrict__ alloc_gate, // [B,1]
    const float* __restrict__ write_gate, // [B,1]
    float* __restrict__ out_link,         // [B,1,N,N]
    float* __restrict__ out_ww,           // [B,N]
    float* __restrict__ out_prec)         // [B,N]
{
    const int blk = blockIdx.x;
    const int b  = blk / (Nn / ROWS_PB);
    const int i0 = (blk % (Nn / ROWS_PB)) * ROWS_PB;
    const int t  = threadIdx.x;
    const int j0 = t * 4;

    const float ag = __ldg(&alloc_gate[b]);
    const float wg = __ldg(&write_gate[b]);
    const float cg = wg * (1.f - ag);
    const float gg = wg * ag;

    float4 Aj = __ldg((const float4*)(g_alloc + (size_t)b * Nn) + t);
    float4 Cj = __ldg((const float4*)(g_wc + (size_t)b * Nn) + t);
    float4 Wj;
    Wj.x = gg * Aj.x + cg * Cj.x;
    Wj.y = gg * Aj.y + cg * Cj.y;
    Wj.z = gg * Aj.z + cg * Cj.z;
    Wj.w = gg * Aj.w + cg * Cj.w;
    float4 Pj = __ldg((const float4*)(prev_prec + (size_t)b * Nn) + t);

    // row weights ww[i0..i0+7]
    float4 Ai0 = __ldg((const float4*)(g_alloc + (size_t)b * Nn + i0));
    float4 Ai1 = __ldg((const float4*)(g_alloc + (size_t)b * Nn + i0 + 4));
    float4 Ci0 = __ldg((const float4*)(g_wc + (size_t)b * Nn + i0));
    float4 Ci1 = __ldg((const float4*)(g_wc + (size_t)b * Nn + i0 + 4));
    float wi_arr[ROWS_PB] = {
        gg * Ai0.x + cg * Ci0.x, gg * Ai0.y + cg * Ci0.y,
        gg * Ai0.z + cg * Ci0.z, gg * Ai0.w + cg * Ci0.w,
        gg * Ai1.x + cg * Ci1.x, gg * Ai1.y + cg * Ci1.y,
        gg * Ai1.z + cg * Ci1.z, gg * Ai1.w + cg * Ci1.w};

    const float4* pl = (const float4*)(prev_link + ((size_t)b * Nn + i0) * Nn) + t;
    float4*       ol = (float4*)(out_link + ((size_t)b * Nn + i0) * Nn) + t;

    float4 L[ROWS_PB];
#pragma unroll
    for (int r = 0; r < ROWS_PB; r++) L[r] = __ldcs(pl + r * (Nn / 4));

#pragma unroll
    for (int r = 0; r < ROWS_PB; r++) {
        int i = i0 + r;
        float wi = wi_arr[r];
        float ci = 1.f - wi;
        float4 o;
        o.x = (ci - Wj.x) * L[r].x + wi * Pj.x;
        o.y = (ci - Wj.y) * L[r].y + wi * Pj.y;
        o.z = (ci - Wj.z) * L[r].z + wi * Pj.z;
        o.w = (ci - Wj.w) * L[r].w + wi * Pj.w;
        int d = i - j0;
        if ((unsigned)d < 4u) ((float*)&o)[d] = 0.f;  // diagonal
        __stcs(ol + r * (Nn / 4), o);
    }

    // one block per batch also emits ww and precedence (t spans all 1024 j)
    if (i0 == 0) {
        float wsum = wg * (ag * __ldg(&g_asum[b]) + (1.f - ag));
        float om = 1.f - wsum;
        ((float4*)(out_ww + (size_t)b * Nn))[t] = Wj;
        float4 pr;
        pr.x = om * Pj.x + Wj.x;
        pr.y = om * Pj.y + Wj.y;
        pr.z = om * Pj.z + Wj.z;
        pr.w = om * Pj.w + Wj.w;
        ((float4*)(out_prec + (size_t)b * Nn))[t] = pr;
    }
}

// ---------------------------------------------------------------------------
// launch
// ---------------------------------------------------------------------------
extern "C" void kernel_launch(void* const* d_in, const int* in_sizes, int n_in,
                              void* d_out, int out_size) {
    const float* memory     = (const float*)d_in[0];
    const float* read_keys  = (const float*)d_in[1];
    const float* read_str   = (const float*)d_in[2];
    const float* write_keys = (const float*)d_in[3];
    const float* write_str  = (const float*)d_in[4];
    const float* free_gate  = (const float*)d_in[5];
    const float* alloc_gate = (const float*)d_in[6];
    const float* write_gate = (const float*)d_in[7];
    const float* prev_rw    = (const float*)d_in[8];
    const float* prev_ww    = (const float*)d_in[9];
    const float* prev_usage = (const float*)d_in[10];
    const float* prev_link  = (const float*)d_in[11];
    const float* prev_prec  = (const float*)d_in[12];

    float* out = (float*)d_out;
    float* out_rw    = out;                                   // [B,R,N]
    float* out_ww    = out_rw + (size_t)Bn * Rn * Nn;         // [B,1,N]
    float* out_usage = out_ww + (size_t)Bn * Nn;              // [B,N]
    float* out_link  = out_usage + (size_t)Bn * Nn;           // [B,1,N,N]
    float* out_prec  = out_link + (size_t)Bn * Nn * Nn;       // [B,1,N]

    dnc_stage1_kernel<<<2 * Bn, 1024>>>(
        memory, read_keys, read_str, write_keys, write_str,
        free_gate, prev_rw, prev_ww, prev_usage,
        out_rw, out_usage);

    dnc_link_kernel<<<(Bn * Nn) / ROWS_PB, 256>>>(
        prev_link, prev_prec, alloc_gate, write_gate,
        out_link, out_ww, out_prec);
}